// round 14
// baseline (speedup 1.0000x reference)
#include <cuda_runtime.h>
#include <math.h>
#include <stdint.h>

// ---------------------------------------------------------------------------
// PPO fused loss on GB300 — two PHASES inside one persistent kernel:
//  Phase A (all 304 CTAs): next_values GEMV, pure coalesced LDG streaming.
//  Phase B (all 304 CTAs): states-only mma.sync tf32 GEMM (actor + values),
//    ring-4 cp.async, issue-before-compute, ONE barrier/slab, SW128 A tiles.
// No inter-phase sync needed: deltas are formed in kgae (launch-ordered).
// ---------------------------------------------------------------------------

#define T_MAX   262144
#define S_DIM   512
#define A_DIM   64
#define BM      128
#define GAMMA_F 0.99f
#define GL_F    (0.99f * 0.98f)
#define CLIP_LO 0.8f
#define CLIP_HI 1.2f
#define ENT_C   0.01f
#define CHUNK   2048
#define NB_MAX  (T_MAX / CHUNK)
#define NGRP    9
#define GRID1   304

// scratch
__device__ float g_v[T_MAX];
__device__ float g_nv[T_MAX];
__device__ float g_ratio[T_MAX];
__device__ float g_ent[T_MAX / BM];
__device__ float g_cA[NB_MAX];
__device__ float g_cB[NB_MAX];
__device__ float g_surr[NB_MAX];
__device__ float g_adv2[NB_MAX];
__device__ int   g_tile;
__device__ int   g_flag;
__device__ int   g_flag2;
__device__ __align__(16) float2 g_wfrag[64 * NGRP * 32];

// ---------------- smem layout ----------------
#define SLABS        16
#define RING         4
#define A_SLAB_BYTES 16384                 // 128 rows x 128B, SW128 swizzled
#define BW_BYTES     (4 * NGRP * 32 * 8)   // 9216
#define STAGE_BYTES  (A_SLAB_BYTES + BW_BYTES)   // 25600
#define OFF_SCW   (RING * STAGE_BYTES)     // 102400
#define OFF_ENT   (OFF_SCW + 2048)         // 104448
#define OFF_NXT   (OFF_ENT + 64)           // 104512
#define SMEM_TOTAL (OFF_NXT + 16)          // 104528 (x2 CTAs = 209056 <= 227KB)

// ---------------- PTX helpers ----------------
__device__ __forceinline__ uint32_t smem_to_u32(const void* p) {
    uint32_t a;
    asm("{ .reg .u64 t; cvta.to.shared.u64 t, %1; cvt.u32.u64 %0, t; }" : "=r"(a) : "l"(p));
    return a;
}
__device__ __forceinline__ void cpa16(uint32_t dst, const void* src) {
    asm volatile("cp.async.cg.shared.global [%0], [%1], 16;" :: "r"(dst), "l"(src) : "memory");
}
#define CP_COMMIT() asm volatile("cp.async.commit_group;" ::: "memory")
#define CP_WAIT2()  asm volatile("cp.async.wait_group 2;" ::: "memory")
#define CP_WAIT0()  asm volatile("cp.async.wait_group 0;" ::: "memory")

__device__ __forceinline__ void mma_tf32(float (&d)[4], const uint32_t (&a)[4],
                                         const uint32_t (&b)[2]) {
    asm volatile(
        "mma.sync.aligned.m16n8k8.row.col.f32.tf32.tf32.f32 "
        "{%0,%1,%2,%3}, {%4,%5,%6,%7}, {%8,%9}, {%0,%1,%2,%3};"
        : "+f"(d[0]), "+f"(d[1]), "+f"(d[2]), "+f"(d[3])
        : "r"(a[0]), "r"(a[1]), "r"(a[2]), "r"(a[3]), "r"(b[0]), "r"(b[1]));
}
__device__ __forceinline__ uint32_t to_tf32(float x) {
    uint32_t r;
    asm("cvt.rna.tf32.f32 %0, %1;" : "=r"(r) : "f"(x));
    return r;
}

// ---------------------------------------------------------------------------
// prep: pack [actor_w | critic_w] into mma B-fragment order + reset counters.
// ---------------------------------------------------------------------------
__global__ void kprep(const float* __restrict__ aw, const float* __restrict__ cw) {
    if (blockIdx.x == 0 && threadIdx.x == 0) { g_tile = 0; g_flag = 0; g_flag2 = 0; }
    int e = blockIdx.x * 256 + threadIdx.x;
    int lane = e & 31, gk = e >> 5;
    int G = gk % NGRP, ks = gk / NGRP;
    int nloc = lane >> 2;
    int k = ks * 8 + (lane & 3);
    float w0, w1;
    if (G < 8) {
        int n = G * 8 + nloc;
        w0 = aw[k * A_DIM + n];
        w1 = aw[(k + 4) * A_DIM + n];
    } else {
        w0 = (nloc == 0) ? cw[k] : 0.f;
        w1 = (nloc == 0) ? cw[k + 4] : 0.f;
    }
    float2 v;
    v.x = __uint_as_float(to_tf32(w0));
    v.y = __uint_as_float(to_tf32(w1));
    g_wfrag[e] = v;
}

// ---------------------------------------------------------------------------
// GEMM slab loader: states slab (tile, s) SW128-swizzled + B window -> buf.
// ---------------------------------------------------------------------------
__device__ __forceinline__ void issue_slab(uint32_t su, int buf, int tile, int s,
                                           const float* __restrict__ states,
                                           int nb1, int tid) {
    if (tile >= nb1) return;
    const uint32_t sbase = su + buf * STAGE_BYTES;
    const size_t goff = (size_t)tile * BM * S_DIM + s * 32;
#pragma unroll
    for (int i = 0; i < 4; ++i) {
        int g = tid + i * 256;                 // 0..1023
        int r = g >> 3, u = g & 7;
        cpa16(sbase + r * 128 + ((u ^ (r & 7)) << 4),
              states + goff + (size_t)r * S_DIM + u * 4);
    }
    const char* bsrc = (const char*)(g_wfrag + (size_t)s * 4 * NGRP * 32);
    cpa16(sbase + A_SLAB_BYTES + tid * 16, bsrc + (size_t)tid * 16);
    {
        int g = tid + 256;
        cpa16(sbase + A_SLAB_BYTES + g * 16, bsrc + (size_t)g * 16);
    }
    if (tid < 64) {
        int g = tid + 512;
        cpa16(sbase + A_SLAB_BYTES + g * 16, bsrc + (size_t)g * 16);
    }
}

// ---------------------------------------------------------------------------
// THE kernel: phase A (GEMV next_values) then phase B (GEMM tiles).
// ---------------------------------------------------------------------------
__global__ void __launch_bounds__(256, 2)
k1_mma(const float* __restrict__ states,
       const float* __restrict__ next_states,
       const int*   __restrict__ actions,
       const float* __restrict__ log_probs,
       const float* __restrict__ actor_b,
       const float* __restrict__ critic_w,
       const float* __restrict__ critic_b,
       int nb1) {
    extern __shared__ __align__(16) char smem[];
    const uint32_t su = smem_to_u32(smem);
    const int tid  = threadIdx.x;
    const int w    = tid >> 5;
    const int lane = tid & 31;
    const int bid = blockIdx.x, gdim = gridDim.x;
    const float cb = critic_b[0];

    float* scw  = (float*)(smem + OFF_SCW);
    float* sEnt = (float*)(smem + OFF_ENT);
    int*   sNxt = (int*)(smem + OFF_NXT);

    // stage critic_w once
    if (tid < 128) ((float4*)scw)[tid] = __ldg(((const float4*)critic_w) + tid);
    __syncthreads();

    // ================= Phase A: next_values GEMV =================
    // 2 threads per row; thread covers 256 contiguous cols.
    {
        const int ch = tid & 1;
        const int rloc = tid >> 1;             // 0..127
        const float4* ws = (const float4*)(scw + ch * 256);
        for (int it = bid; it < nb1; it += gdim) {
            const int row = it * BM + rloc;
            const float4* xs = (const float4*)(next_states + (size_t)row * S_DIM + ch * 256);
            float acc = 0.f;
#pragma unroll 8
            for (int i = 0; i < 64; ++i) {
                float4 x = __ldg(xs + i);
                float4 wv = ws[i];
                acc = fmaf(x.x, wv.x, fmaf(x.y, wv.y,
                      fmaf(x.z, wv.z, fmaf(x.w, wv.w, acc))));
            }
            acc += __shfl_xor_sync(0xffffffffu, acc, 1);
            if (ch == 0) g_nv[row] = acc + cb;
        }
    }

    // ================= Phase B: GEMM tiles =================
    const int q = lane >> 2, j = lane & 3;

    float2 bias[8];
#pragma unroll
    for (int g = 0; g < 8; ++g)
        bias[g] = __ldg((const float2*)(actor_b + g * 8 + j * 2));

    __syncthreads();
    if (tid == 0) sNxt[1] = atomicAdd(&g_tile, 1);
    __syncthreads();
    int cur = sNxt[1];
    issue_slab(su, 0, cur, 0, states, nb1, tid); CP_COMMIT();
    issue_slab(su, 1, cur, 1, states, nb1, tid); CP_COMMIT();
    issue_slab(su, 2, cur, 2, states, nb1, tid); CP_COMMIT();

    const int rowA = 16 * w + q;
    const int swr = rowA & 7;

    while (cur < nb1) {
        const int row0 = cur * BM;

        float acc[8][4];
        float accV[4];
#pragma unroll
        for (int g = 0; g < 8; ++g)
#pragma unroll
            for (int p = 0; p < 4; ++p) acc[g][p] = 0.f;
#pragma unroll
        for (int p = 0; p < 4; ++p) accV[p] = 0.f;

        for (int s = 0; s < SLABS; ++s) {
            CP_WAIT2();                 // slab s resident (s+1, s+2 in flight)
            __syncthreads();            // all warps done with buf (s+3)&3 (slab s-1)
            if (s == 0 && tid == 0) sNxt[0] = atomicAdd(&g_tile, 1);
            {
                const int nxt = s + 3;
                const int t2 = (nxt < SLABS) ? cur : sNxt[0];
                issue_slab(su, nxt & 3, t2, nxt & (SLABS - 1), states, nb1, tid);
                CP_COMMIT();
            }

            const char* stage = smem + (size_t)(s & 3) * STAGE_BYTES;
            const char* Ar0 = stage + rowA * 128 + j * 4;
            const char* Ar1 = stage + (rowA + 8) * 128 + j * 4;
            const float2* Bw = (const float2*)(stage + A_SLAB_BYTES);

#pragma unroll
            for (int ks = 0; ks < 4; ++ks) {
                uint32_t af[4];
                const int sw0 = ((2 * ks) ^ swr) << 4;
                const int sw1 = ((2 * ks + 1) ^ swr) << 4;
                af[0] = *(const uint32_t*)(Ar0 + sw0);
                af[1] = *(const uint32_t*)(Ar1 + sw0);
                af[2] = *(const uint32_t*)(Ar0 + sw1);
                af[3] = *(const uint32_t*)(Ar1 + sw1);

                const float2* Bk = Bw + (size_t)ks * NGRP * 32 + lane;
                uint32_t bfc[2];
                {
                    float2 v = Bk[8 * 32];
                    bfc[0] = __float_as_uint(v.x);
                    bfc[1] = __float_as_uint(v.y);
                }
#pragma unroll
                for (int g = 0; g < 8; ++g) {
                    uint32_t bf[2];
                    float2 v = Bk[g * 32];
                    bf[0] = __float_as_uint(v.x);
                    bf[1] = __float_as_uint(v.y);
                    mma_tf32(acc[g], af, bf);
                }
                mma_tf32(accV, af, bfc);   // values
            }
        }

        // ---- register epilogue: writes g_v / g_ratio / g_ent ----
        float ent2 = 0.f;
#pragma unroll
        for (int half = 0; half < 2; ++half) {
            float tl[8][2];
            float m = -1e30f;
#pragma unroll
            for (int g = 0; g < 8; ++g) {
                tl[g][0] = acc[g][half * 2]     + bias[g].x;
                tl[g][1] = acc[g][half * 2 + 1] + bias[g].y;
                m = fmaxf(m, fmaxf(tl[g][0], tl[g][1]));
            }
            m = fmaxf(m, __shfl_xor_sync(0xffffffffu, m, 1));
            m = fmaxf(m, __shfl_xor_sync(0xffffffffu, m, 2));

            float se = 0.f, pe = 0.f;
#pragma unroll
            for (int g = 0; g < 8; ++g) {
#pragma unroll
                for (int b = 0; b < 2; ++b) {
                    float t = tl[g][b] - m;
                    tl[g][b] = t;
                    float e = __expf(t);
                    se += e;
                    pe = fmaf(e, t, pe);
                }
            }
            se += __shfl_xor_sync(0xffffffffu, se, 1);
            se += __shfl_xor_sync(0xffffffffu, se, 2);
            pe += __shfl_xor_sync(0xffffffffu, pe, 1);
            pe += __shfl_xor_sync(0xffffffffu, pe, 2);

            const int r = 16 * w + q + half * 8;
            const int grow = row0 + r;
            const int a = __ldg(actions + grow);
            float cand = -1e30f;
            if (j == ((a >> 1) & 3)) {
                const int ga = a >> 3, ba = a & 1;
#pragma unroll
                for (int g = 0; g < 8; ++g)
                    if (g == ga) cand = ba ? tl[g][1] : tl[g][0];
            }
            cand = fmaxf(cand, __shfl_xor_sync(0xffffffffu, cand, 1));
            cand = fmaxf(cand, __shfl_xor_sync(0xffffffffu, cand, 2));

            if (j == 0) {
                const float logse = __logf(se);
                g_ratio[grow] = __expf(cand - logse - __ldg(log_probs + grow));
                g_v[grow] = accV[half * 2] + cb;
                ent2 += logse - pe / se;
            }
        }
#pragma unroll
        for (int o = 16; o > 0; o >>= 1) ent2 += __shfl_xor_sync(0xffffffffu, ent2, o);
        if (lane == 0) sEnt[w] = ent2;
        __syncthreads();
        if (tid == 0) {
            float s8 = 0.f;
#pragma unroll
            for (int i = 0; i < 8; ++i) s8 += sEnt[i];
            g_ent[cur] = s8;
        }
        cur = sNxt[0];
    }
    CP_WAIT0();
}

// ---------------------------------------------------------------------------
// GAE: deltas inline from g_v/g_nv (validated in R12); spin-synced exchange.
// ---------------------------------------------------------------------------
__device__ __forceinline__ void thread_affine(const float* __restrict__ rewards,
                                              const int* __restrict__ dones,
                                              int base, float (&d)[8], float (&c)[8],
                                              float& A, float& Bv) {
    float4 v0 = *(const float4*)&g_v[base];
    float4 v1 = *(const float4*)&g_v[base + 4];
    float4 n0 = *(const float4*)&g_nv[base];
    float4 n1 = *(const float4*)&g_nv[base + 4];
    float4 r0 = *(const float4*)&rewards[base];
    float4 r1 = *(const float4*)&rewards[base + 4];
    int4 q0 = *(const int4*)&dones[base];
    int4 q1 = *(const int4*)&dones[base + 4];
    float nd[8] = {1.f-(float)q0.x, 1.f-(float)q0.y, 1.f-(float)q0.z, 1.f-(float)q0.w,
                   1.f-(float)q1.x, 1.f-(float)q1.y, 1.f-(float)q1.z, 1.f-(float)q1.w};
    float vv[8] = {v0.x, v0.y, v0.z, v0.w, v1.x, v1.y, v1.z, v1.w};
    float nn[8] = {n0.x, n0.y, n0.z, n0.w, n1.x, n1.y, n1.z, n1.w};
    float rr[8] = {r0.x, r0.y, r0.z, r0.w, r1.x, r1.y, r1.z, r1.w};
#pragma unroll
    for (int i = 0; i < 8; ++i) {
        d[i] = rr[i] + GAMMA_F * nn[i] * nd[i] - vv[i];
        c[i] = GL_F * nd[i];
    }
    A = 1.f; Bv = 0.f;
#pragma unroll
    for (int jj = 7; jj >= 0; --jj) { Bv = fmaf(c[jj], Bv, d[jj]); A = c[jj] * A; }
}

__global__ void __launch_bounds__(256)
kgae(const float* __restrict__ rewards, const int* __restrict__ dones,
     int nb, float* __restrict__ out, int T, int nb1) {
    __shared__ float sa[256], sb[256];
    __shared__ float ca[NB_MAX], cbv[NB_MAX];
    __shared__ float sv_[256];
    __shared__ int sdone;
    const int tid = threadIdx.x;
    const int blk = blockIdx.x;
    const int base = blk * CHUNK + tid * 8;

    float d[8], c[8], A, Bv;
    thread_affine(rewards, dones, base, d, c, A, Bv);

    sa[tid] = A; sb[tid] = Bv;
    __syncthreads();
    for (int dd = 1; dd < 256; dd <<= 1) {
        float al = sa[tid], bl = sb[tid];
        float ar = 1.f, br = 0.f;
        if (tid + dd < 256) { ar = sa[tid + dd]; br = sb[tid + dd]; }
        __syncthreads();
        sa[tid] = al * ar;
        sb[tid] = fmaf(al, br, bl);
        __syncthreads();
    }

    if (tid == 0) {
        g_cA[blk] = sa[0];
        g_cB[blk] = sb[0];
        __threadfence();
        atomicAdd(&g_flag, 1);
        while (*(volatile int*)&g_flag < nb) { }
    }
    __syncthreads();
    __threadfence();

    if (tid < NB_MAX) { ca[tid] = g_cA[tid]; cbv[tid] = g_cB[tid]; }
    __syncthreads();
    for (int dd = 1; dd < NB_MAX; dd <<= 1) {
        float a = 0.f, b = 0.f, ar = 1.f, br = 0.f;
        if (tid < NB_MAX) {
            a = ca[tid]; b = cbv[tid];
            if (tid + dd < NB_MAX) { ar = ca[tid + dd]; br = cbv[tid + dd]; }
        }
        __syncthreads();
        if (tid < NB_MAX) { ca[tid] = a * ar; cbv[tid] = fmaf(a, br, b); }
        __syncthreads();
    }
    const float xb = (blk + 1 < nb) ? cbv[blk + 1] : 0.f;
    float xin = (tid == 255) ? xb : fmaf(sa[tid + 1], xb, sb[tid + 1]);

    float4 r0 = *(const float4*)&g_ratio[base];
    float4 r1 = *(const float4*)&g_ratio[base + 4];
    float rt[8] = {r0.x, r0.y, r0.z, r0.w, r1.x, r1.y, r1.z, r1.w};

    float adv = xin, s1 = 0.f, s2 = 0.f;
#pragma unroll
    for (int jj = 7; jj >= 0; --jj) {
        adv = fmaf(c[jj], adv, d[jj]);
        const float r = rt[jj];
        const float rc = fminf(fmaxf(r, CLIP_LO), CLIP_HI);
        s1 += fminf(r * adv, rc * adv);
        s2 = fmaf(adv, adv, s2);
    }
    __syncthreads();
    sa[tid] = s1; sb[tid] = s2;
    __syncthreads();
    for (int s = 128; s > 0; s >>= 1) {
        if (tid < s) { sa[tid] += sa[tid + s]; sb[tid] += sb[tid + s]; }
        __syncthreads();
    }
    if (tid == 0) {
        g_surr[blk] = sa[0];
        g_adv2[blk] = sb[0];
        __threadfence();
        sdone = atomicAdd(&g_flag2, 1);
    }
    __syncthreads();

    if (sdone == nb - 1) {
        __threadfence();
        float e = 0.f, s = 0.f, v = 0.f;
        for (int i = tid; i < nb1; i += 256) e += g_ent[i];
        for (int i = tid; i < nb; i += 256) { s += g_surr[i]; v += g_adv2[i]; }
        __syncthreads();
        sa[tid] = e; sb[tid] = s; sv_[tid] = v;
        __syncthreads();
        for (int st = 128; st > 0; st >>= 1) {
            if (tid < st) {
                sa[tid] += sa[tid + st];
                sb[tid] += sb[tid + st];
                sv_[tid] += sv_[tid + st];
            }
            __syncthreads();
        }
        if (tid == 0) {
            const float invT = 1.f / (float)T;
            out[0] = -(sb[0] * invT) - ENT_C * (sa[0] * invT);
            out[1] = sv_[0] * invT;
        }
    }
}

extern "C" void kernel_launch(void* const* d_in, const int* in_sizes, int n_in,
                              void* d_out, int out_size) {
    const float* states      = (const float*)d_in[0];
    const float* next_states = (const float*)d_in[1];
    const float* rewards     = (const float*)d_in[2];
    const int*   dones       = (const int*)  d_in[3];
    const int*   actions     = (const int*)  d_in[4];
    const float* log_probs   = (const float*)d_in[5];
    const float* actor_w     = (const float*)d_in[6];
    const float* actor_b     = (const float*)d_in[7];
    const float* critic_w    = (const float*)d_in[8];
    const float* critic_b    = (const float*)d_in[9];
    float* out = (float*)d_out;

    const int T   = in_sizes[2];
    const int nb1 = T / BM;       // 2048
    const int nb  = T / CHUNK;    // 128
    const int grid1 = nb1 < GRID1 ? nb1 : GRID1;

    cudaFuncSetAttribute(k1_mma, cudaFuncAttributeMaxDynamicSharedMemorySize, SMEM_TOTAL);

    kprep<<<(64 * NGRP * 32) / 256, 256>>>(actor_w, critic_w);
    k1_mma<<<grid1, 256, SMEM_TOTAL>>>(states, next_states, actions, log_probs,
                                       actor_b, critic_w, critic_b, nb1);
    kgae<<<nb, 256>>>(rewards, dones, nb, out, T, nb1);
}

// round 15
// speedup vs baseline: 1.3651x; 1.3651x over previous
#include <cuda_runtime.h>
#include <math.h>
#include <stdint.h>

// ---------------------------------------------------------------------------
// PPO fused loss on GB300 — R8 math with warp specialization:
//  warps 0..7 (256 thr): consumers — mma.sync tf32 GEMM + epilogue (R8 exact)
//  warps 8..9 (64 thr):  producers — all cp.async, CP_WAIT, tile scheduling
// Named-barrier full/free/header protocol; ring-2 stages identical to R8.
// ---------------------------------------------------------------------------

#define T_MAX   262144
#define S_DIM   512
#define A_DIM   64
#define BM      128
#define GAMMA_F 0.99f
#define GL_F    (0.99f * 0.98f)
#define CLIP_LO 0.8f
#define CLIP_HI 1.2f
#define ENT_C   0.01f
#define CHUNK   2048
#define NB_MAX  (T_MAX / CHUNK)
#define NGRP    9
#define GRID1   304
#define NTHR    320
#define NCONS   256

// named barrier ids
#define BFULL0  1
#define BFREE0  3
#define BHDR    5
#define BEPI    6
#define BPROD   7

// scratch
__device__ float g_delta[T_MAX];
__device__ float g_ratio[T_MAX];
__device__ float g_ent[T_MAX / BM];
__device__ float g_cA[NB_MAX];
__device__ float g_cB[NB_MAX];
__device__ float g_surr[NB_MAX];
__device__ float g_adv2[NB_MAX];
__device__ int   g_tile;
__device__ int   g_flag;
__device__ int   g_flag2;
__device__ __align__(16) float2 g_wfrag[64 * NGRP * 32];

// ---------------- smem layout (R8 stages) ----------------
#define SLABS        16
#define A_ROW_F      36
#define SLAB_BYTES   (128 * 144)
#define BW_BYTES     (4 * NGRP * 32 * 8)
#define STAGE_BYTES  (2 * SLAB_BYTES + BW_BYTES)   // 46080
#define OFF_ENT   (2 * STAGE_BYTES)                // 92160
#define OFF_Q     (OFF_ENT + 64)                   // 92224 : int[8] tile ring
#define SMEM_TOTAL (OFF_Q + 64)                    // 92288 (x2 <= 227KB)

// ---------------- PTX helpers ----------------
__device__ __forceinline__ uint32_t smem_to_u32(const void* p) {
    uint32_t a;
    asm("{ .reg .u64 t; cvta.to.shared.u64 t, %1; cvt.u32.u64 %0, t; }" : "=r"(a) : "l"(p));
    return a;
}
__device__ __forceinline__ void cpa16(uint32_t dst, const void* src) {
    asm volatile("cp.async.cg.shared.global [%0], [%1], 16;" :: "r"(dst), "l"(src) : "memory");
}
#define CP_COMMIT() asm volatile("cp.async.commit_group;" ::: "memory")
#define CP_WAIT1()  asm volatile("cp.async.wait_group 1;" ::: "memory")
#define CP_WAIT0()  asm volatile("cp.async.wait_group 0;" ::: "memory")
#define BAR_SYNC(id, cnt)   asm volatile("bar.sync %0, %1;"   :: "r"(id), "r"(cnt) : "memory")
#define BAR_ARRIVE(id, cnt) asm volatile("bar.arrive %0, %1;" :: "r"(id), "r"(cnt) : "memory")

__device__ __forceinline__ void mma_tf32(float (&d)[4], const uint32_t (&a)[4],
                                         const uint32_t (&b)[2]) {
    asm volatile(
        "mma.sync.aligned.m16n8k8.row.col.f32.tf32.tf32.f32 "
        "{%0,%1,%2,%3}, {%4,%5,%6,%7}, {%8,%9}, {%0,%1,%2,%3};"
        : "+f"(d[0]), "+f"(d[1]), "+f"(d[2]), "+f"(d[3])
        : "r"(a[0]), "r"(a[1]), "r"(a[2]), "r"(a[3]), "r"(b[0]), "r"(b[1]));
}
__device__ __forceinline__ uint32_t to_tf32(float x) {
    uint32_t r;
    asm("cvt.rna.tf32.f32 %0, %1;" : "=r"(r) : "f"(x));
    return r;
}

// ---------------------------------------------------------------------------
// prep: pack [actor_w | critic_w] into mma B-fragment order + reset counters.
// ---------------------------------------------------------------------------
__global__ void kprep(const float* __restrict__ aw, const float* __restrict__ cw) {
    if (blockIdx.x == 0 && threadIdx.x == 0) { g_tile = 0; g_flag = 0; g_flag2 = 0; }
    int e = blockIdx.x * 256 + threadIdx.x;
    int lane = e & 31, gk = e >> 5;
    int G = gk % NGRP, ks = gk / NGRP;
    int nloc = lane >> 2;
    int k = ks * 8 + (lane & 3);
    float w0, w1;
    if (G < 8) {
        int n = G * 8 + nloc;
        w0 = aw[k * A_DIM + n];
        w1 = aw[(k + 4) * A_DIM + n];
    } else {
        w0 = (nloc == 0) ? cw[k] : 0.f;
        w1 = (nloc == 0) ? cw[k + 4] : 0.f;
    }
    float2 v;
    v.x = __uint_as_float(to_tf32(w0));
    v.y = __uint_as_float(to_tf32(w1));
    g_wfrag[e] = v;
}

// ---------------------------------------------------------------------------
// producer slab loader (64 threads): states + next_states + B window.
// ---------------------------------------------------------------------------
__device__ __forceinline__ void issue_slab64(uint32_t su, int buf, int tile, int s,
                                             const float* __restrict__ states,
                                             const float* __restrict__ next_states,
                                             int ptid) {
    const uint32_t sbase = su + buf * STAGE_BYTES;
    const size_t goff = (size_t)tile * BM * S_DIM + s * 32;
#pragma unroll
    for (int i = 0; i < 32; ++i) {
        int g = ptid + i * 64;                 // 0..2047
        int mtx = g >> 10;
        int r = (g & 1023) >> 3, u = g & 7;
        const float* src = (mtx ? next_states : states) + goff + (size_t)r * S_DIM + u * 4;
        cpa16(sbase + mtx * SLAB_BYTES + r * 144 + u * 16, src);
    }
    const char* bsrc = (const char*)(g_wfrag + (size_t)s * 4 * NGRP * 32);
#pragma unroll
    for (int i = 0; i < 9; ++i) {
        int g = ptid + i * 64;                 // 0..575
        cpa16(sbase + 2 * SLAB_BYTES + g * 16, bsrc + (size_t)g * 16);
    }
}

// ---------------------------------------------------------------------------
// Main kernel: producer/consumer warp specialization.
// ---------------------------------------------------------------------------
__global__ void __launch_bounds__(NTHR, 2)
k1_mma(const float* __restrict__ states,
       const float* __restrict__ next_states,
       const float* __restrict__ rewards,
       const int*   __restrict__ dones,
       const int*   __restrict__ actions,
       const float* __restrict__ log_probs,
       const float* __restrict__ actor_b,
       const float* __restrict__ critic_b,
       int nb1) {
    extern __shared__ __align__(16) char smem[];
    const uint32_t su = smem_to_u32(smem);
    const int tid  = threadIdx.x;
    const int w    = tid >> 5;
    const int lane = tid & 31;

    float* sEnt = (float*)(smem + OFF_ENT);
    int*   sQ   = (int*)(smem + OFF_Q);

    if (w >= 8) {
        // ===================== PRODUCERS (warps 8,9) =====================
        const int ptid = tid - NCONS;
        int pend = -1;
        for (int i = 0;; ++i) {
            if (ptid == 0) sQ[i & 7] = atomicAdd(&g_tile, 1);
            BAR_SYNC(BPROD, 64);                    // sQ visible to producers
            const int t = sQ[i & 7];
            BAR_ARRIVE(BHDR, NTHR);                 // header ready for consumers
            if (t >= nb1) break;
#pragma unroll 1
            for (int s = 0; s < SLABS; ++s) {
                const int buf = s & 1;
                if (i > 0 || s >= 2) BAR_SYNC(BFREE0 + buf, NTHR);
                issue_slab64(su, buf, t, s, states, next_states, ptid);
                CP_COMMIT();
                if (pend >= 0) {
                    CP_WAIT1();                     // previous slab's group done
                    BAR_ARRIVE(BFULL0 + pend, NTHR);
                }
                pend = buf;
            }
        }
        if (pend >= 0) {
            CP_WAIT0();                             // final slab complete
            BAR_ARRIVE(BFULL0 + pend, NTHR);
        }
        return;
    }

    // ===================== CONSUMERS (warps 0..7) =====================
    const int q = lane >> 2, j = lane & 3;
    const float cb = critic_b[0];

    float2 bias[8];
#pragma unroll
    for (int g = 0; g < 8; ++g)
        bias[g] = __ldg((const float2*)(actor_b + g * 8 + j * 2));

    for (int i = 0;; ++i) {
        BAR_SYNC(BHDR, NTHR);                       // wait tile header
        const int cur = sQ[i & 7];
        if (cur >= nb1) break;
        const int row0 = cur * BM;

        float acc[8][4];
        float accV[4], accN[4];
#pragma unroll
        for (int g = 0; g < 8; ++g)
#pragma unroll
            for (int p = 0; p < 4; ++p) acc[g][p] = 0.f;
#pragma unroll
        for (int p = 0; p < 4; ++p) { accV[p] = 0.f; accN[p] = 0.f; }

        for (int s = 0; s < SLABS; ++s) {
            const int buf = s & 1;
            BAR_SYNC(BFULL0 + buf, NTHR);           // slab resident

            const char* stage = smem + (size_t)buf * STAGE_BYTES;
            const float* Ar = (const float*)stage + (16 * w + q) * A_ROW_F + j;
            const float* Nr = (const float*)(stage + SLAB_BYTES) + (16 * w + q) * A_ROW_F + j;
            const float2* Bw = (const float2*)(stage + 2 * SLAB_BYTES);

#pragma unroll
            for (int ks = 0; ks < 4; ++ks) {
                uint32_t af[4], an[4];
                const float* Am = Ar + ks * 8;
                af[0] = __float_as_uint(Am[0]);
                af[1] = __float_as_uint(Am[8 * A_ROW_F]);
                af[2] = __float_as_uint(Am[4]);
                af[3] = __float_as_uint(Am[8 * A_ROW_F + 4]);
                const float* Nm = Nr + ks * 8;
                an[0] = __float_as_uint(Nm[0]);
                an[1] = __float_as_uint(Nm[8 * A_ROW_F]);
                an[2] = __float_as_uint(Nm[4]);
                an[3] = __float_as_uint(Nm[8 * A_ROW_F + 4]);

                const float2* Bk = Bw + (size_t)ks * NGRP * 32 + lane;
                uint32_t bfc[2];
                {
                    float2 v = Bk[8 * 32];
                    bfc[0] = __float_as_uint(v.x);
                    bfc[1] = __float_as_uint(v.y);
                }
#pragma unroll
                for (int g = 0; g < 8; ++g) {
                    uint32_t bf[2];
                    float2 v = Bk[g * 32];
                    bf[0] = __float_as_uint(v.x);
                    bf[1] = __float_as_uint(v.y);
                    mma_tf32(acc[g], af, bf);
                }
                mma_tf32(accV, af, bfc);            // values
                mma_tf32(accN, an, bfc);            // next_values
            }
            BAR_ARRIVE(BFREE0 + buf, NTHR);         // buffer free (non-blocking)
        }

        // ---- register epilogue (R8 exact, consumer-only barriers) ----
        float ent2 = 0.f;
#pragma unroll
        for (int half = 0; half < 2; ++half) {
            float tl[8][2];
            float m = -1e30f;
#pragma unroll
            for (int g = 0; g < 8; ++g) {
                tl[g][0] = acc[g][half * 2]     + bias[g].x;
                tl[g][1] = acc[g][half * 2 + 1] + bias[g].y;
                m = fmaxf(m, fmaxf(tl[g][0], tl[g][1]));
            }
            m = fmaxf(m, __shfl_xor_sync(0xffffffffu, m, 1));
            m = fmaxf(m, __shfl_xor_sync(0xffffffffu, m, 2));

            float se = 0.f, pe = 0.f;
#pragma unroll
            for (int g = 0; g < 8; ++g) {
#pragma unroll
                for (int b = 0; b < 2; ++b) {
                    float t = tl[g][b] - m;
                    tl[g][b] = t;
                    float e = __expf(t);
                    se += e;
                    pe = fmaf(e, t, pe);
                }
            }
            se += __shfl_xor_sync(0xffffffffu, se, 1);
            se += __shfl_xor_sync(0xffffffffu, se, 2);
            pe += __shfl_xor_sync(0xffffffffu, pe, 1);
            pe += __shfl_xor_sync(0xffffffffu, pe, 2);

            const int r = 16 * w + q + half * 8;
            const int grow = row0 + r;
            const int a = __ldg(actions + grow);
            float cand = -1e30f;
            if (j == ((a >> 1) & 3)) {
                const int ga = a >> 3, ba = a & 1;
#pragma unroll
                for (int g = 0; g < 8; ++g)
                    if (g == ga) cand = ba ? tl[g][1] : tl[g][0];
            }
            cand = fmaxf(cand, __shfl_xor_sync(0xffffffffu, cand, 1));
            cand = fmaxf(cand, __shfl_xor_sync(0xffffffffu, cand, 2));

            if (j == 0) {
                const float logse = __logf(se);
                const float ratio = __expf(cand - logse - __ldg(log_probs + grow));
                const float nd = 1.f - (float)__ldg(dones + grow);
                const float v  = accV[half * 2] + cb;
                const float nv = accN[half * 2] + cb;
                g_delta[grow] = __ldg(rewards + grow) + GAMMA_F * nv * nd - v;
                g_ratio[grow] = ratio;
                ent2 += logse - pe / se;
            }
        }
#pragma unroll
        for (int o = 16; o > 0; o >>= 1) ent2 += __shfl_xor_sync(0xffffffffu, ent2, o);
        if (lane == 0) sEnt[w] = ent2;
        BAR_SYNC(BEPI, NCONS);
        if (tid == 0) {
            float s8 = 0.f;
#pragma unroll
            for (int i2 = 0; i2 < 8; ++i2) s8 += sEnt[i2];
            g_ent[cur] = s8;
        }
    }
}

// ---------------------------------------------------------------------------
// Single-kernel GAE (exact R8 body)
// ---------------------------------------------------------------------------
__device__ __forceinline__ void thread_affine(const int* __restrict__ dones,
                                              int base, float (&d)[8], float (&c)[8],
                                              float& A, float& Bv) {
    float4 d0 = *(const float4*)&g_delta[base];
    float4 d1 = *(const float4*)&g_delta[base + 4];
    int4 q0 = *(const int4*)&dones[base];
    int4 q1 = *(const int4*)&dones[base + 4];
    d[0]=d0.x; d[1]=d0.y; d[2]=d0.z; d[3]=d0.w;
    d[4]=d1.x; d[5]=d1.y; d[6]=d1.z; d[7]=d1.w;
    c[0]=GL_F*(1.f-(float)q0.x); c[1]=GL_F*(1.f-(float)q0.y);
    c[2]=GL_F*(1.f-(float)q0.z); c[3]=GL_F*(1.f-(float)q0.w);
    c[4]=GL_F*(1.f-(float)q1.x); c[5]=GL_F*(1.f-(float)q1.y);
    c[6]=GL_F*(1.f-(float)q1.z); c[7]=GL_F*(1.f-(float)q1.w);
    A = 1.f; Bv = 0.f;
#pragma unroll
    for (int jj = 7; jj >= 0; --jj) { Bv = fmaf(c[jj], Bv, d[jj]); A = c[jj] * A; }
}

__global__ void __launch_bounds__(256)
kgae(const int* __restrict__ dones, int nb, float* __restrict__ out, int T, int nb1) {
    __shared__ float sa[256], sb[256];
    __shared__ float ca[NB_MAX], cbv[NB_MAX];
    __shared__ float sv_[256];
    __shared__ int sdone;
    const int tid = threadIdx.x;
    const int blk = blockIdx.x;
    const int base = blk * CHUNK + tid * 8;

    float d[8], c[8], A, Bv;
    thread_affine(dones, base, d, c, A, Bv);

    sa[tid] = A; sb[tid] = Bv;
    __syncthreads();
    for (int dd = 1; dd < 256; dd <<= 1) {
        float al = sa[tid], bl = sb[tid];
        float ar = 1.f, br = 0.f;
        if (tid + dd < 256) { ar = sa[tid + dd]; br = sb[tid + dd]; }
        __syncthreads();
        sa[tid] = al * ar;
        sb[tid] = fmaf(al, br, bl);
        __syncthreads();
    }

    if (tid == 0) {
        g_cA[blk] = sa[0];
        g_cB[blk] = sb[0];
        __threadfence();
        atomicAdd(&g_flag, 1);
        while (*(volatile int*)&g_flag < nb) { }
    }
    __syncthreads();
    __threadfence();

    if (tid < NB_MAX) { ca[tid] = g_cA[tid]; cbv[tid] = g_cB[tid]; }
    __syncthreads();
    for (int dd = 1; dd < NB_MAX; dd <<= 1) {
        float a = 0.f, b = 0.f, ar = 1.f, br = 0.f;
        if (tid < NB_MAX) {
            a = ca[tid]; b = cbv[tid];
            if (tid + dd < NB_MAX) { ar = ca[tid + dd]; br = cbv[tid + dd]; }
        }
        __syncthreads();
        if (tid < NB_MAX) { ca[tid] = a * ar; cbv[tid] = fmaf(a, br, b); }
        __syncthreads();
    }
    const float xb = (blk + 1 < nb) ? cbv[blk + 1] : 0.f;
    float xin = (tid == 255) ? xb : fmaf(sa[tid + 1], xb, sb[tid + 1]);

    float4 r0 = *(const float4*)&g_ratio[base];
    float4 r1 = *(const float4*)&g_ratio[base + 4];
    float rt[8] = {r0.x, r0.y, r0.z, r0.w, r1.x, r1.y, r1.z, r1.w};

    float adv = xin, s1 = 0.f, s2 = 0.f;
#pragma unroll
    for (int jj = 7; jj >= 0; --jj) {
        adv = fmaf(c[jj], adv, d[jj]);
        const float r = rt[jj];
        const float rc = fminf(fmaxf(r, CLIP_LO), CLIP_HI);
        s1 += fminf(r * adv, rc * adv);
        s2 = fmaf(adv, adv, s2);
    }
    __syncthreads();
    sa[tid] = s1; sb[tid] = s2;
    __syncthreads();
    for (int s = 128; s > 0; s >>= 1) {
        if (tid < s) { sa[tid] += sa[tid + s]; sb[tid] += sb[tid + s]; }
        __syncthreads();
    }
    if (tid == 0) {
        g_surr[blk] = sa[0];
        g_adv2[blk] = sb[0];
        __threadfence();
        sdone = atomicAdd(&g_flag2, 1);
    }
    __syncthreads();

    if (sdone == nb - 1) {
        __threadfence();
        float e = 0.f, s = 0.f, v = 0.f;
        for (int i = tid; i < nb1; i += 256) e += g_ent[i];
        for (int i = tid; i < nb; i += 256) { s += g_surr[i]; v += g_adv2[i]; }
        __syncthreads();
        sa[tid] = e; sb[tid] = s; sv_[tid] = v;
        __syncthreads();
        for (int st = 128; st > 0; st >>= 1) {
            if (tid < st) {
                sa[tid] += sa[tid + st];
                sb[tid] += sb[tid + st];
                sv_[tid] += sv_[tid + st];
            }
            __syncthreads();
        }
        if (tid == 0) {
            const float invT = 1.f / (float)T;
            out[0] = -(sb[0] * invT) - ENT_C * (sa[0] * invT);
            out[1] = sv_[0] * invT;
        }
    }
}

extern "C" void kernel_launch(void* const* d_in, const int* in_sizes, int n_in,
                              void* d_out, int out_size) {
    const float* states      = (const float*)d_in[0];
    const float* next_states = (const float*)d_in[1];
    const float* rewards     = (const float*)d_in[2];
    const int*   dones       = (const int*)  d_in[3];
    const int*   actions     = (const int*)  d_in[4];
    const float* log_probs   = (const float*)d_in[5];
    const float* actor_w     = (const float*)d_in[6];
    const float* actor_b     = (const float*)d_in[7];
    const float* critic_w    = (const float*)d_in[8];
    const float* critic_b    = (const float*)d_in[9];
    float* out = (float*)d_out;

    const int T   = in_sizes[2];
    const int nb1 = T / BM;       // 2048
    const int nb  = T / CHUNK;    // 128
    const int grid1 = nb1 < GRID1 ? nb1 : GRID1;

    cudaFuncSetAttribute(k1_mma, cudaFuncAttributeMaxDynamicSharedMemorySize, SMEM_TOTAL);

    kprep<<<(64 * NGRP * 32) / 256, 256>>>(actor_w, critic_w);
    k1_mma<<<grid1, NTHR, SMEM_TOTAL>>>(states, next_states, rewards, dones, actions,
                                        log_probs, actor_b, critic_b, nb1);
    kgae<<<nb, 256>>>(dones, nb, out, T, nb1);
}